// round 2
// baseline (speedup 1.0000x reference)
#include <cuda_runtime.h>
#include <cstdint>

// Problem constants (fixed by the reference)
#define Bn   4
#define Cn   128
#define HWn  16384      // 128*128
#define Pn   4096
#define Vn   32
#define PT   32         // points per block in gather kernel

// Scratch for transposed x: [B][HW][C] float = 33.5 MB (device global, no alloc)
__device__ float g_xt[(size_t)Bn * HWn * Cn];

// ---------------------------------------------------------------------------
// Kernel 1: transpose x [B,C,HW] -> g_xt [B,HW,C]
// 32x32 tiles, 32x8 threads.
// ---------------------------------------------------------------------------
__global__ __launch_bounds__(256) void transpose_kernel(const float* __restrict__ x)
{
    __shared__ float tile[32][33];

    const int b   = blockIdx.z;
    const int hw0 = blockIdx.x * 32;
    const int c0  = blockIdx.y * 32;
    const int tx  = threadIdx.x;   // 0..31
    const int ty  = threadIdx.y;   // 0..7

    // load: tile[c_local][hw_local]
    #pragma unroll
    for (int j = 0; j < 4; j++) {
        int c = c0 + ty + j * 8;
        tile[ty + j * 8][tx] = x[((size_t)b * Cn + c) * HWn + hw0 + tx];
    }
    __syncthreads();

    // store: xt[b][hw][c], coalesced in c
    #pragma unroll
    for (int j = 0; j < 4; j++) {
        int hw = hw0 + ty + j * 8;
        g_xt[((size_t)b * HWn + hw) * Cn + c0 + tx] = tile[tx][ty + j * 8];
    }
}

// ---------------------------------------------------------------------------
// Kernel 2: gather + weighted accumulate.
// Block: 256 threads (8 warps), handles (b, 32 points).
// Warp w processes points w, w+8, w+16, w+24. Lane l owns channels 4l..4l+3
// (float4). Inner loop over 32 votes: fully coalesced 512B gathers from g_xt.
// Output staged in smem and written coalesced along P (contiguous dim).
// ---------------------------------------------------------------------------
__global__ __launch_bounds__(256) void gather_kernel(
    const int*   __restrict__ vote_index,   // [32768, 32]
    const float* __restrict__ vote_weight,  // [32768, 32]
    const int*   __restrict__ inds,         // [B, P] int32 (JAX x64 disabled)
    float*       __restrict__ out)          // [B, C, P]
{
    __shared__ int   s_idx[PT][Vn];
    __shared__ float s_w  [PT][Vn];
    __shared__ float s_out[PT][132];   // 132-pad: float4-aligned rows, reduces rd conflicts

    const int b  = blockIdx.y;
    const int p0 = blockIdx.x * PT;
    const int t  = threadIdx.x;

    // Stage vote indices + weights for 32 points: thread t loads 4 entries.
    {
        const int pl = t >> 3;              // 0..31
        const int v4 = (t & 7) * 4;         // 0..28
        const int sph = inds[(size_t)b * Pn + p0 + pl];
        const int4*   vi = reinterpret_cast<const int4*>(vote_index + (size_t)sph * Vn + v4);
        const float4* vw = reinterpret_cast<const float4*>(vote_weight + (size_t)sph * Vn + v4);
        *reinterpret_cast<int4*>(&s_idx[pl][v4])   = *vi;
        *reinterpret_cast<float4*>(&s_w[pl][v4])   = *vw;
    }
    __syncthreads();

    const int warp = t >> 5;
    const int lane = t & 31;
    const float4* xt4 = reinterpret_cast<const float4*>(g_xt) + (size_t)b * HWn * (Cn / 4);

    #pragma unroll
    for (int pi = warp; pi < PT; pi += 8) {
        float4 acc = make_float4(0.f, 0.f, 0.f, 0.f);
        #pragma unroll 8
        for (int v = 0; v < Vn; v++) {
            const int   hw = s_idx[pi][v];   // warp-uniform broadcast
            const float w  = s_w[pi][v];
            const float4 g = __ldg(&xt4[(size_t)hw * (Cn / 4) + lane]);
            acc.x = fmaf(g.x, w, acc.x);
            acc.y = fmaf(g.y, w, acc.y);
            acc.z = fmaf(g.z, w, acc.z);
            acc.w = fmaf(g.w, w, acc.w);
        }
        *reinterpret_cast<float4*>(&s_out[pi][lane * 4]) = acc;
    }
    __syncthreads();

    // Write out [C][PT] tile: consecutive threads -> consecutive p (coalesced 128B)
    #pragma unroll
    for (int i = t; i < Cn * PT; i += 256) {
        const int c  = i >> 5;   // i / PT
        const int pl = i & 31;   // i % PT
        out[((size_t)b * Cn + c) * Pn + p0 + pl] = s_out[pl][c];
    }
}

// ---------------------------------------------------------------------------
// Launch
// ---------------------------------------------------------------------------
extern "C" void kernel_launch(void* const* d_in, const int* in_sizes, int n_in,
                              void* d_out, int out_size)
{
    const float* x           = (const float*)d_in[0];   // [4,128,128,128]
    const int*   vote_index  = (const int*)d_in[1];     // [32768,32]
    const float* vote_weight = (const float*)d_in[2];   // [32768,32]
    const int*   inds        = (const int*)d_in[3];     // [4,4096] int32
    float*       out         = (float*)d_out;           // [4,128,4096]

    {
        dim3 grid(HWn / 32, Cn / 32, Bn);   // (512, 4, 4)
        dim3 block(32, 8);
        transpose_kernel<<<grid, block>>>(x);
    }
    {
        dim3 grid(Pn / PT, Bn);             // (128, 4)
        gather_kernel<<<grid, 256>>>(vote_index, vote_weight, inds, out);
    }
}

// round 3
// speedup vs baseline: 1.0937x; 1.0937x over previous
#include <cuda_runtime.h>
#include <cstdint>

// Problem constants (fixed by the reference)
#define Bn   4
#define Cn   128
#define HWn  16384      // 128*128
#define Pn   4096
#define Vn   32
#define PT   8          // points per block in gather kernel (1 warp per point)

// Scratch for transposed x: [B][HW][C] float = 33.5 MB (device global, no alloc)
__device__ float g_xt[(size_t)Bn * HWn * Cn];

// ---------------------------------------------------------------------------
// Kernel 1: transpose x [B,C,HW] -> g_xt [B,HW,C]
// 32x32 tiles, 32x8 threads.
// ---------------------------------------------------------------------------
__global__ __launch_bounds__(256) void transpose_kernel(const float* __restrict__ x)
{
    __shared__ float tile[32][33];

    const int b   = blockIdx.z;
    const int hw0 = blockIdx.x * 32;
    const int c0  = blockIdx.y * 32;
    const int tx  = threadIdx.x;   // 0..31
    const int ty  = threadIdx.y;   // 0..7

    #pragma unroll
    for (int j = 0; j < 4; j++) {
        int c = c0 + ty + j * 8;
        tile[ty + j * 8][tx] = x[((size_t)b * Cn + c) * HWn + hw0 + tx];
    }
    __syncthreads();

    #pragma unroll
    for (int j = 0; j < 4; j++) {
        int hw = hw0 + ty + j * 8;
        g_xt[((size_t)b * HWn + hw) * Cn + c0 + tx] = tile[tx][ty + j * 8];
    }
}

// ---------------------------------------------------------------------------
// Kernel 2: gather + weighted accumulate. ONE WARP PER POINT.
// Block: 256 threads (8 warps) -> 8 points. Grid: (P/8, B) = (512, 4) = 2048
// blocks (13.8/SM, fills residency; round-2 grid of 512 left SMs at 43% occ).
// Lane l owns channels 4l..4l+3 (float4): each vote is one coalesced 512B LDG.
// Two accumulators break the FMA chain; votes are fully independent loads.
// ---------------------------------------------------------------------------
__global__ __launch_bounds__(256, 6) void gather_kernel(
    const int*   __restrict__ vote_index,   // [32768, 32]
    const float* __restrict__ vote_weight,  // [32768, 32]
    const int*   __restrict__ inds,         // [B, P] int32
    float*       __restrict__ out)          // [B, C, P]
{
    __shared__ int   s_idx[PT][Vn];
    __shared__ float s_w  [PT][Vn];
    __shared__ float s_out[PT][132];   // pad to keep float4 rows conflict-light

    const int b  = blockIdx.y;
    const int p0 = blockIdx.x * PT;
    const int t  = threadIdx.x;
    const int warp = t >> 5;
    const int lane = t & 31;

    // Stage vote indices + weights: thread t loads one (point, vote) pair.
    {
        const int pl = warp;                // 0..7
        const int v  = lane;                // 0..31
        const int sph = inds[(size_t)b * Pn + p0 + pl];   // warp-uniform load
        s_idx[pl][v] = vote_index[(size_t)sph * Vn + v];
        s_w[pl][v]   = vote_weight[(size_t)sph * Vn + v];
    }
    __syncthreads();

    const float4* xt4 = reinterpret_cast<const float4*>(g_xt) + (size_t)b * HWn * (Cn / 4);

    // Warp `warp` processes point p0+warp: 32 independent coalesced gathers.
    {
        float4 acc0 = make_float4(0.f, 0.f, 0.f, 0.f);
        float4 acc1 = make_float4(0.f, 0.f, 0.f, 0.f);
        #pragma unroll 8
        for (int v = 0; v < Vn; v += 2) {
            const int   hw0_ = s_idx[warp][v];
            const int   hw1_ = s_idx[warp][v + 1];
            const float w0   = s_w[warp][v];
            const float w1   = s_w[warp][v + 1];
            const float4 g0 = __ldg(&xt4[(size_t)hw0_ * (Cn / 4) + lane]);
            const float4 g1 = __ldg(&xt4[(size_t)hw1_ * (Cn / 4) + lane]);
            acc0.x = fmaf(g0.x, w0, acc0.x);
            acc0.y = fmaf(g0.y, w0, acc0.y);
            acc0.z = fmaf(g0.z, w0, acc0.z);
            acc0.w = fmaf(g0.w, w0, acc0.w);
            acc1.x = fmaf(g1.x, w1, acc1.x);
            acc1.y = fmaf(g1.y, w1, acc1.y);
            acc1.z = fmaf(g1.z, w1, acc1.z);
            acc1.w = fmaf(g1.w, w1, acc1.w);
        }
        acc0.x += acc1.x; acc0.y += acc1.y; acc0.z += acc1.z; acc0.w += acc1.w;
        *reinterpret_cast<float4*>(&s_out[warp][lane * 4]) = acc0;
    }
    __syncthreads();

    // Write out [C][PT] tile: 8 consecutive p per c row (32B segments).
    #pragma unroll
    for (int i = t; i < Cn * PT; i += 256) {
        const int c  = i >> 3;   // i / PT
        const int pl = i & 7;    // i % PT
        out[((size_t)b * Cn + c) * Pn + p0 + pl] = s_out[pl][c];
    }
}

// ---------------------------------------------------------------------------
// Launch
// ---------------------------------------------------------------------------
extern "C" void kernel_launch(void* const* d_in, const int* in_sizes, int n_in,
                              void* d_out, int out_size)
{
    const float* x           = (const float*)d_in[0];   // [4,128,128,128]
    const int*   vote_index  = (const int*)d_in[1];     // [32768,32]
    const float* vote_weight = (const float*)d_in[2];   // [32768,32]
    const int*   inds        = (const int*)d_in[3];     // [4,4096] int32
    float*       out         = (float*)d_out;           // [4,128,4096]

    {
        dim3 grid(HWn / 32, Cn / 32, Bn);   // (512, 4, 4)
        dim3 block(32, 8);
        transpose_kernel<<<grid, block>>>(x);
    }
    {
        dim3 grid(Pn / PT, Bn);             // (512, 4) = 2048 blocks
        gather_kernel<<<grid, 256>>>(vote_index, vote_weight, inds, out);
    }
}

// round 4
// speedup vs baseline: 1.4620x; 1.3367x over previous
#include <cuda_runtime.h>
#include <cuda_fp16.h>
#include <cstdint>

// Problem constants (fixed by the reference)
#define Bn   4
#define Cn   128
#define HWn  16384      // 128*128
#define Pn   4096
#define Vn   32
#define PT   8          // points per block in gather kernel (1 warp per point)

// Scratch for transposed x in fp16: [B][HW][C] half = 16.8 MB.
// fp16 halves the L2 gather traffic (the measured LTS cap was binding at fp32).
__device__ __align__(16) __half g_xt[(size_t)Bn * HWn * Cn];

// ---------------------------------------------------------------------------
// Kernel 1: transpose + downconvert x [B,C,HW] fp32 -> g_xt [B,HW,C] fp16.
// Tile: 64 c x 32 hw. Block 32x8. Stores are half2-packed, 128B/warp coalesced.
// ---------------------------------------------------------------------------
__global__ __launch_bounds__(256) void transpose_fp16_kernel(const float* __restrict__ x)
{
    __shared__ float tile[64][33];

    const int b   = blockIdx.z;
    const int hw0 = blockIdx.x * 32;
    const int c0  = blockIdx.y * 64;
    const int tx  = threadIdx.x;   // 0..31
    const int ty  = threadIdx.y;   // 0..7

    #pragma unroll
    for (int j = 0; j < 8; j++) {
        const int cl = ty + j * 8;                       // 0..63
        tile[cl][tx] = x[((size_t)b * Cn + c0 + cl) * HWn + hw0 + tx];
    }
    __syncthreads();

    const int t = ty * 32 + tx;                          // 0..255
    __half2* xt2 = reinterpret_cast<__half2*>(g_xt);
    #pragma unroll
    for (int j = 0; j < 4; j++) {
        const int idx  = j * 256 + t;                    // 0..1023
        const int hw_l = idx >> 5;                       // 0..31
        const int c2   = idx & 31;                       // 0..31 (half2 index)
        const float f0 = tile[c2 * 2][hw_l];
        const float f1 = tile[c2 * 2 + 1][hw_l];
        xt2[(((size_t)b * HWn + hw0 + hw_l) * Cn + c0) / 2 + c2] = __floats2half2_rn(f0, f1);
    }
}

// ---------------------------------------------------------------------------
// Kernel 2: gather + weighted accumulate. ONE WARP PER POINT, fp16 gathers.
// Block: 256 threads (8 warps) -> 8 points. Grid: (512, 4) = 2048 blocks.
// Lane l owns channels 4l..4l+3 = one uint2 (4 halves): each vote is a single
// coalesced 256B warp gather. Accumulation in fp32, dual accumulators.
// ---------------------------------------------------------------------------
__global__ __launch_bounds__(256, 6) void gather_kernel(
    const int*   __restrict__ vote_index,   // [32768, 32]
    const float* __restrict__ vote_weight,  // [32768, 32]
    const int*   __restrict__ inds,         // [B, P] int32
    float*       __restrict__ out)          // [B, C, P]
{
    __shared__ int   s_idx[PT][Vn];
    __shared__ float s_w  [PT][Vn];
    __shared__ float s_out[PT][132];

    const int b    = blockIdx.y;
    const int p0   = blockIdx.x * PT;
    const int t    = threadIdx.x;
    const int warp = t >> 5;
    const int lane = t & 31;

    // Stage vote indices + weights: warp w stages point p0+w (lane = vote).
    {
        const int sph = inds[(size_t)b * Pn + p0 + warp];   // warp-uniform
        s_idx[warp][lane] = vote_index[(size_t)sph * Vn + lane];
        s_w[warp][lane]   = vote_weight[(size_t)sph * Vn + lane];
    }
    __syncthreads();

    // Row = 128 halves = 32 uint2; lane l reads uint2 l (channels 4l..4l+3).
    const uint2* xt = reinterpret_cast<const uint2*>(g_xt) + (size_t)b * HWn * (Cn / 4);

    {
        float4 acc0 = make_float4(0.f, 0.f, 0.f, 0.f);
        float4 acc1 = make_float4(0.f, 0.f, 0.f, 0.f);
        #pragma unroll 8
        for (int v = 0; v < Vn; v += 2) {
            const int   hwa = s_idx[warp][v];
            const int   hwb = s_idx[warp][v + 1];
            const float wa  = s_w[warp][v];
            const float wb  = s_w[warp][v + 1];
            const uint2 ra = __ldg(&xt[(size_t)hwa * (Cn / 4) + lane]);
            const uint2 rb = __ldg(&xt[(size_t)hwb * (Cn / 4) + lane]);
            const float2 a0 = __half22float2(*reinterpret_cast<const __half2*>(&ra.x));
            const float2 a1 = __half22float2(*reinterpret_cast<const __half2*>(&ra.y));
            const float2 b0 = __half22float2(*reinterpret_cast<const __half2*>(&rb.x));
            const float2 b1 = __half22float2(*reinterpret_cast<const __half2*>(&rb.y));
            acc0.x = fmaf(a0.x, wa, acc0.x);
            acc0.y = fmaf(a0.y, wa, acc0.y);
            acc0.z = fmaf(a1.x, wa, acc0.z);
            acc0.w = fmaf(a1.y, wa, acc0.w);
            acc1.x = fmaf(b0.x, wb, acc1.x);
            acc1.y = fmaf(b0.y, wb, acc1.y);
            acc1.z = fmaf(b1.x, wb, acc1.z);
            acc1.w = fmaf(b1.y, wb, acc1.w);
        }
        acc0.x += acc1.x; acc0.y += acc1.y; acc0.z += acc1.z; acc0.w += acc1.w;
        *reinterpret_cast<float4*>(&s_out[warp][lane * 4]) = acc0;
    }
    __syncthreads();

    // Write out [C][PT] tile: 8 consecutive p per c row (32B segments).
    #pragma unroll
    for (int i = t; i < Cn * PT; i += 256) {
        const int c  = i >> 3;   // i / PT
        const int pl = i & 7;    // i % PT
        out[((size_t)b * Cn + c) * Pn + p0 + pl] = s_out[pl][c];
    }
}

// ---------------------------------------------------------------------------
// Launch
// ---------------------------------------------------------------------------
extern "C" void kernel_launch(void* const* d_in, const int* in_sizes, int n_in,
                              void* d_out, int out_size)
{
    const float* x           = (const float*)d_in[0];   // [4,128,128,128]
    const int*   vote_index  = (const int*)d_in[1];     // [32768,32]
    const float* vote_weight = (const float*)d_in[2];   // [32768,32]
    const int*   inds        = (const int*)d_in[3];     // [4,4096] int32
    float*       out         = (float*)d_out;           // [4,128,4096]

    {
        dim3 grid(HWn / 32, Cn / 64, Bn);   // (512, 2, 4)
        dim3 block(32, 8);
        transpose_fp16_kernel<<<grid, block>>>(x);
    }
    {
        dim3 grid(Pn / PT, Bn);             // (512, 4) = 2048 blocks
        gather_kernel<<<grid, 256>>>(vote_index, vote_weight, inds, out);
    }
}

// round 5
// speedup vs baseline: 1.5887x; 1.0867x over previous
#include <cuda_runtime.h>
#include <cuda_fp16.h>
#include <cstdint>

// Problem constants (fixed by the reference)
#define Bn   4
#define Cn   128
#define HWn  16384      // 128*128
#define Pn   4096
#define Vn   32
#define PT   8          // points per block in gather kernel (1 warp per point)

// Scratch for transposed x in fp16: [B][HW][C] half = 16.8 MB.
__device__ __align__(16) __half g_xt[(size_t)Bn * HWn * Cn];

// ---------------------------------------------------------------------------
// Kernel 1: transpose + downconvert x [B,C,HW] fp32 -> g_xt [B,HW,C] fp16.
// Tile: 64 c x 32 hw. Block 32x8. Stores are half2-packed, coalesced.
// DRAM-bound at ~50MB total; already near roofline (~7us).
// ---------------------------------------------------------------------------
__global__ __launch_bounds__(256) void transpose_fp16_kernel(const float* __restrict__ x)
{
    __shared__ float tile[64][33];

    const int b   = blockIdx.z;
    const int hw0 = blockIdx.x * 32;
    const int c0  = blockIdx.y * 64;
    const int tx  = threadIdx.x;   // 0..31
    const int ty  = threadIdx.y;   // 0..7

    #pragma unroll
    for (int j = 0; j < 8; j++) {
        const int cl = ty + j * 8;
        tile[cl][tx] = x[((size_t)b * Cn + c0 + cl) * HWn + hw0 + tx];
    }
    __syncthreads();

    const int t = ty * 32 + tx;
    __half2* xt2 = reinterpret_cast<__half2*>(g_xt);
    #pragma unroll
    for (int j = 0; j < 4; j++) {
        const int idx  = j * 256 + t;
        const int hw_l = idx >> 5;
        const int c2   = idx & 31;
        const float f0 = tile[c2 * 2][hw_l];
        const float f1 = tile[c2 * 2 + 1][hw_l];
        xt2[(((size_t)b * HWn + hw0 + hw_l) * Cn + c0) / 2 + c2] = __floats2half2_rn(f0, f1);
    }
}

// ---------------------------------------------------------------------------
// Kernel 2: gather + vote accumulate. ONE WARP PER POINT, issue-slot lean.
// Per vote per lane: 1 LDS.64 (fused idx+weight) + 1 LDG.64 + 2 HFMA2.
// fp16 partials are flushed to fp32 accumulators every 4 votes.
// ---------------------------------------------------------------------------
__global__ __launch_bounds__(256, 6) void gather_kernel(
    const int*   __restrict__ vote_index,   // [32768, 32]
    const float* __restrict__ vote_weight,  // [32768, 32]
    const int*   __restrict__ inds,         // [B, P] int32
    float*       __restrict__ out)          // [B, C, P]
{
    __shared__ uint2 s_iw[PT][Vn];   // {hw * (Cn/4), half2(w,w) bits}
    __shared__ float s_out[PT][132];

    const int b    = blockIdx.y;
    const int p0   = blockIdx.x * PT;
    const int t    = threadIdx.x;
    const int warp = t >> 5;
    const int lane = t & 31;

    // Stage fused (offset, weight-half2) per vote. Warp w stages point p0+w.
    {
        const int sph = inds[(size_t)b * Pn + p0 + warp];   // warp-uniform
        const int hw  = vote_index[(size_t)sph * Vn + lane];
        const float w = vote_weight[(size_t)sph * Vn + lane];
        const __half2 w2 = __float2half2_rn(w);
        s_iw[warp][lane] = make_uint2((unsigned)hw * (Cn / 4),
                                      *reinterpret_cast<const unsigned*>(&w2));
    }
    __syncthreads();

    // Row = 128 halves = 32 uint2; lane l owns uint2 l (channels 4l..4l+3).
    const uint2* xt = reinterpret_cast<const uint2*>(g_xt) + (size_t)b * HWn * (Cn / 4);

    {
        float2 accA = make_float2(0.f, 0.f);
        float2 accB = make_float2(0.f, 0.f);

        #pragma unroll
        for (int g = 0; g < Vn / 4; g++) {           // 8 groups of 4 votes
            // Issue the 4 independent gathers first (MLP), then HFMA2 chain.
            uint2 iw[4], r[4];
            #pragma unroll
            for (int k = 0; k < 4; k++) {
                iw[k] = s_iw[warp][g * 4 + k];
                r[k]  = __ldg(&xt[iw[k].x + lane]);
            }
            __half2 a0 = __float2half2_rn(0.f);
            __half2 a1 = __float2half2_rn(0.f);
            #pragma unroll
            for (int k = 0; k < 4; k++) {
                const __half2 w2 = *reinterpret_cast<const __half2*>(&iw[k].y);
                a0 = __hfma2(*reinterpret_cast<const __half2*>(&r[k].x), w2, a0);
                a1 = __hfma2(*reinterpret_cast<const __half2*>(&r[k].y), w2, a1);
            }
            // Flush fp16 partials into fp32 accumulators.
            const float2 f0 = __half22float2(a0);
            const float2 f1 = __half22float2(a1);
            accA.x += f0.x; accA.y += f0.y;
            accB.x += f1.x; accB.y += f1.y;
        }
        float4 acc = make_float4(accA.x, accA.y, accB.x, accB.y);
        *reinterpret_cast<float4*>(&s_out[warp][lane * 4]) = acc;
    }
    __syncthreads();

    // Write out [C][PT] tile: 8 consecutive p per c row.
    #pragma unroll
    for (int i = t; i < Cn * PT; i += 256) {
        const int c  = i >> 3;   // i / PT
        const int pl = i & 7;    // i % PT
        out[((size_t)b * Cn + c) * Pn + p0 + pl] = s_out[pl][c];
    }
}

// ---------------------------------------------------------------------------
// Launch
// ---------------------------------------------------------------------------
extern "C" void kernel_launch(void* const* d_in, const int* in_sizes, int n_in,
                              void* d_out, int out_size)
{
    const float* x           = (const float*)d_in[0];   // [4,128,128,128]
    const int*   vote_index  = (const int*)d_in[1];     // [32768,32]
    const float* vote_weight = (const float*)d_in[2];   // [32768,32]
    const int*   inds        = (const int*)d_in[3];     // [4,4096] int32
    float*       out         = (float*)d_out;           // [4,128,4096]

    {
        dim3 grid(HWn / 32, Cn / 64, Bn);   // (512, 2, 4)
        dim3 block(32, 8);
        transpose_fp16_kernel<<<grid, block>>>(x);
    }
    {
        dim3 grid(Pn / PT, Bn);             // (512, 4) = 2048 blocks
        gather_kernel<<<grid, 256>>>(vote_index, vote_weight, inds, out);
    }
}

// round 6
// speedup vs baseline: 1.6064x; 1.0111x over previous
#include <cuda_runtime.h>
#include <cuda_fp16.h>
#include <cstdint>

// Problem constants (fixed by the reference)
#define Bn   4
#define Cn   128
#define HWn  16384      // 128*128
#define Pn   4096
#define Vn   32
#define PT   8          // points per block in gather kernel (1 warp per point)

// Scratch for transposed x in fp16: [B][HW][C] half = 16.8 MB.
__device__ __align__(16) __half g_xt[(size_t)Bn * HWn * Cn];

// ---------------------------------------------------------------------------
// Kernel 1: transpose + downconvert x [B,C,HW] fp32 -> g_xt [B,HW,C] fp16.
// ---------------------------------------------------------------------------
__global__ __launch_bounds__(256) void transpose_fp16_kernel(const float* __restrict__ x)
{
    __shared__ float tile[64][33];

    const int b   = blockIdx.z;
    const int hw0 = blockIdx.x * 32;
    const int c0  = blockIdx.y * 64;
    const int tx  = threadIdx.x;   // 0..31
    const int ty  = threadIdx.y;   // 0..7

    #pragma unroll
    for (int j = 0; j < 8; j++) {
        const int cl = ty + j * 8;
        tile[cl][tx] = x[((size_t)b * Cn + c0 + cl) * HWn + hw0 + tx];
    }
    __syncthreads();

    const int t = ty * 32 + tx;
    __half2* xt2 = reinterpret_cast<__half2*>(g_xt);
    #pragma unroll
    for (int j = 0; j < 4; j++) {
        const int idx  = j * 256 + t;
        const int hw_l = idx >> 5;
        const int c2   = idx & 31;
        const float f0 = tile[c2 * 2][hw_l];
        const float f1 = tile[c2 * 2 + 1][hw_l];
        xt2[(((size_t)b * HWn + hw0 + hw_l) * Cn + c0) / 2 + c2] = __floats2half2_rn(f0, f1);
    }
}

// ---------------------------------------------------------------------------
// Kernel 2: gather + vote accumulate. ONE WARP PER POINT.
// Two votes per LDG.128: lanes 0-15 serve vote v (lane lh owns channels
// 8lh..8lh+7 = one uint4 of halves), lanes 16-31 serve vote v+1.
// Group of 8 votes = 4 independent LDG.128 (4KB in flight per warp).
// fp16 HFMA2 partials flushed to fp32 per group; cross-half shfl at the end.
// ---------------------------------------------------------------------------
__global__ __launch_bounds__(256, 6) void gather_kernel(
    const int*   __restrict__ vote_index,   // [32768, 32]
    const float* __restrict__ vote_weight,  // [32768, 32]
    const int*   __restrict__ inds,         // [B, P] int32
    float*       __restrict__ out)          // [B, C, P]
{
    __shared__ uint2 s_iw[PT][Vn];   // {hw * 16 (uint4 row offset), half2(w,w)}
    __shared__ float s_out[PT][132];

    const int b    = blockIdx.y;
    const int p0   = blockIdx.x * PT;
    const int t    = threadIdx.x;
    const int warp = t >> 5;
    const int lane = t & 31;
    const int vsel = lane >> 4;      // which of the 2 votes this half-warp serves
    const int lh   = lane & 15;      // uint4 index within the 128-channel row

    // Stage fused (row offset in uint4 units, weight half2) per vote.
    {
        const int sph = inds[(size_t)b * Pn + p0 + warp];   // warp-uniform
        const int hw  = vote_index[(size_t)sph * Vn + lane];
        const float w = vote_weight[(size_t)sph * Vn + lane];
        const __half2 w2 = __float2half2_rn(w);
        s_iw[warp][lane] = make_uint2((unsigned)hw * 16u,
                                      *reinterpret_cast<const unsigned*>(&w2));
    }
    __syncthreads();

    // Row = 128 halves = 256B = 16 uint4. Batch base in uint4 units.
    const uint4* xt = reinterpret_cast<const uint4*>(g_xt) + (size_t)b * HWn * 16;

    float2 acc[4];   // 8 fp32 channels per lane
    #pragma unroll
    for (int k = 0; k < 4; k++) acc[k] = make_float2(0.f, 0.f);

    #pragma unroll
    for (int g = 0; g < Vn / 8; g++) {   // 4 groups x 8 votes
        // 4 independent LDG.128 (each covers 2 votes across the warp halves)
        uint2 iw[4]; uint4 r[4];
        #pragma unroll
        for (int i = 0; i < 4; i++) {
            iw[i] = s_iw[warp][g * 8 + 2 * i + vsel];
            r[i]  = __ldg(&xt[iw[i].x + lh]);
        }
        __half2 h[4];
        #pragma unroll
        for (int k = 0; k < 4; k++) h[k] = __float2half2_rn(0.f);
        #pragma unroll
        for (int i = 0; i < 4; i++) {
            const __half2 w2 = *reinterpret_cast<const __half2*>(&iw[i].y);
            h[0] = __hfma2(*reinterpret_cast<const __half2*>(&r[i].x), w2, h[0]);
            h[1] = __hfma2(*reinterpret_cast<const __half2*>(&r[i].y), w2, h[1]);
            h[2] = __hfma2(*reinterpret_cast<const __half2*>(&r[i].z), w2, h[2]);
            h[3] = __hfma2(*reinterpret_cast<const __half2*>(&r[i].w), w2, h[3]);
        }
        #pragma unroll
        for (int k = 0; k < 4; k++) {
            const float2 f = __half22float2(h[k]);
            acc[k].x += f.x;
            acc[k].y += f.y;
        }
    }

    // Merge even-vote (lanes 0-15) and odd-vote (lanes 16-31) partials.
    #pragma unroll
    for (int k = 0; k < 4; k++) {
        acc[k].x += __shfl_xor_sync(0xFFFFFFFFu, acc[k].x, 16);
        acc[k].y += __shfl_xor_sync(0xFFFFFFFFu, acc[k].y, 16);
    }

    // Lanes 0-15 hold the final 8 channels each -> write 2 float4s.
    if (vsel == 0) {
        float4 o0 = make_float4(acc[0].x, acc[0].y, acc[1].x, acc[1].y);
        float4 o1 = make_float4(acc[2].x, acc[2].y, acc[3].x, acc[3].y);
        *reinterpret_cast<float4*>(&s_out[warp][lh * 8])     = o0;
        *reinterpret_cast<float4*>(&s_out[warp][lh * 8 + 4]) = o1;
    }
    __syncthreads();

    // Write out [C][PT] tile: 8 consecutive p per c row.
    #pragma unroll
    for (int i = t; i < Cn * PT; i += 256) {
        const int c  = i >> 3;   // i / PT
        const int pl = i & 7;    // i % PT
        out[((size_t)b * Cn + c) * Pn + p0 + pl] = s_out[pl][c];
    }
}

// ---------------------------------------------------------------------------
// Launch
// ---------------------------------------------------------------------------
extern "C" void kernel_launch(void* const* d_in, const int* in_sizes, int n_in,
                              void* d_out, int out_size)
{
    const float* x           = (const float*)d_in[0];   // [4,128,128,128]
    const int*   vote_index  = (const int*)d_in[1];     // [32768,32]
    const float* vote_weight = (const float*)d_in[2];   // [32768,32]
    const int*   inds        = (const int*)d_in[3];     // [4,4096] int32
    float*       out         = (float*)d_out;           // [4,128,4096]

    {
        dim3 grid(HWn / 32, Cn / 64, Bn);   // (512, 2, 4)
        dim3 block(32, 8);
        transpose_fp16_kernel<<<grid, block>>>(x);
    }
    {
        dim3 grid(Pn / PT, Bn);             // (512, 4) = 2048 blocks
        gather_kernel<<<grid, 256>>>(vote_index, vote_weight, inds, out);
    }
}